// round 15
// baseline (speedup 1.0000x reference)
#include <cuda_runtime.h>
#include <cuda_bf16.h>
#include <cuda_fp16.h>
#include <math.h>
#include <stdint.h>

// Problem constants (fixed by dataset)
#define BATCH 4
#define SEQ   1024
#define HEADS 16
#define HDIM  128
#define EMB   (HEADS * HDIM)        // 2048
#define TOTAL (BATCH * SEQ)         // 4096
#define E3    (3 * EMB)             // 6144

#define SCALE     1024.0f
#define INV_S2    (1.0f / 1048576.0f)

#define NSM_SLOTS 296               // 148 SMs x 2 CTAs (96KB smem, <=128 regs)

// ---------------------------------------------------------------------------
// Device scratch (allocation-free rule: __device__ globals)
// ---------------------------------------------------------------------------
__device__ __half g_hid_hi[(size_t)TOTAL * EMB];          // 1024*hidden (hi only)
__device__ __half g_wqkvt_hi[(size_t)E3 * EMB];           // [N=6144,K=2048]
__device__ __half g_wqkvt_lo[(size_t)E3 * EMB];
__device__ __half g_wprojt_hi[(size_t)EMB * EMB];         // [N=2048,K=2048]
__device__ __half g_wprojt_lo[(size_t)EMB * EMB];
__device__ __half g_qkv_hi[(size_t)TOTAL * E3];           // 1024*qkv (hi only)
__device__ __half g_ctx_hi[(size_t)TOTAL * EMB];          // 1024*ctx (hi only)

// ---------------------------------------------------------------------------
// PTX helpers
// ---------------------------------------------------------------------------
__device__ __forceinline__ uint32_t smem_u32(const void* p) {
    uint32_t a;
    asm("{ .reg .u64 t; cvta.to.shared.u64 t, %1; cvt.u32.u64 %0, t; }"
        : "=r"(a) : "l"(p));
    return a;
}
__device__ __forceinline__ void cp_async16(uint32_t dst, const void* src) {
    asm volatile("cp.async.cg.shared.global [%0], [%1], 16;"
                 :: "r"(dst), "l"(src) : "memory");
}
#define CP_COMMIT() asm volatile("cp.async.commit_group;" ::: "memory")
#define CP_WAIT(n)  asm volatile("cp.async.wait_group %0;" :: "n"(n) : "memory")

__device__ __forceinline__ void ldsm_x4(uint32_t* r, uint32_t addr) {
    asm volatile("ldmatrix.sync.aligned.m8n8.x4.shared.b16 {%0,%1,%2,%3}, [%4];"
                 : "=r"(r[0]), "=r"(r[1]), "=r"(r[2]), "=r"(r[3]) : "r"(addr));
}
__device__ __forceinline__ void ldsm_x4_t(uint32_t* r, uint32_t addr) {
    asm volatile("ldmatrix.sync.aligned.m8n8.x4.trans.shared.b16 {%0,%1,%2,%3}, [%4];"
                 : "=r"(r[0]), "=r"(r[1]), "=r"(r[2]), "=r"(r[3]) : "r"(addr));
}
__device__ __forceinline__ void mma_f16(float* d, const uint32_t* a,
                                        const uint32_t* b) {
    asm volatile(
        "mma.sync.aligned.m16n8k16.row.col.f32.f16.f16.f32 "
        "{%0,%1,%2,%3}, {%4,%5,%6,%7}, {%8,%9}, {%0,%1,%2,%3};"
        : "+f"(d[0]), "+f"(d[1]), "+f"(d[2]), "+f"(d[3])
        : "r"(a[0]), "r"(a[1]), "r"(a[2]), "r"(a[3]), "r"(b[0]), "r"(b[1]));
}
__device__ __forceinline__ uint32_t pack_h2(float x, float y) {
    __half2 t = __floats2half2_rn(x, y);
    return *(uint32_t*)&t;
}

// ---------------------------------------------------------------------------
// Convert (hi only): H = fp16(1024 * X)
// ---------------------------------------------------------------------------
__global__ void convert_hi_kernel(const float* __restrict__ X,
                                  __half* __restrict__ H, int n4)
{
    int i = blockIdx.x * blockDim.x + threadIdx.x;
    if (i >= n4) return;
    float4 v = ((const float4*)X)[i];
    uint32_t o[2];
    o[0] = pack_h2(v.x * SCALE, v.y * SCALE);
    o[1] = pack_h2(v.z * SCALE, v.w * SCALE);
    *(uint2*)(H + i * 4) = *(uint2*)o;
}

// ---------------------------------------------------------------------------
// Transpose + split: X[K,N] fp32 -> T[N,K] fp16 hi/lo of (1024*X)
// ---------------------------------------------------------------------------
__global__ void transpose_split_kernel(const float* __restrict__ X,
                                       __half* __restrict__ TH,
                                       __half* __restrict__ TL,
                                       int K, int N)
{
    __shared__ float tile[32][33];
    int n0 = blockIdx.x * 32, k0 = blockIdx.y * 32;
    int tx = threadIdx.x, ty = threadIdx.y;
#pragma unroll
    for (int i = 0; i < 4; i++)
        tile[ty + i * 8][tx] = X[(size_t)(k0 + ty + i * 8) * N + n0 + tx];
    __syncthreads();
#pragma unroll
    for (int i = 0; i < 4; i++) {
        int n = n0 + ty + i * 8;
        int k = k0 + tx;
        float v = tile[tx][ty + i * 8] * SCALE;
        __half hi = __float2half_rn(v);
        __half lo = __float2half_rn(v - __half2float(hi));
        TH[(size_t)n * K + k] = hi;
        TL[(size_t)n * K + k] = lo;
    }
}

// ---------------------------------------------------------------------------
// Persistent fp16 2-product GEMM via mma.sync:
//   C = Ah @ (Bh+Bl)^T * 2^-20 + bias
// BM=BN=128, BK=32, 256 threads, 8 warps (2x4), warp tile 64x32.
// 4-stage cp.async ring, grid = NSM_SLOTS, each CTA loops over tiles.
// mode 0: fp32 Cf out. mode 1: fp16 Ch out (hi only).
// ---------------------------------------------------------------------------
#define GS_BUF   8192
#define GS_STAGE 24576
#define GS_NSTG  4
#define GSMEM_TOTAL (GS_NSTG * GS_STAGE)   // 96 KB

__device__ __forceinline__ void gemm_load_stage(
    uint32_t sbase, const __half* __restrict__ Ah,
    const __half* __restrict__ Bh, const __half* __restrict__ Bl,
    int m0, int n0, int K, int k0, int tid)
{
    const __half* bufs[3] = {Ah, Bh, Bl};
#pragma unroll
    for (int i = 0; i < 6; i++) {
        const int idx = tid + i * 256;        // 0..1535
        const int buf = idx >> 9;             // 0..2
        const int r = (idx >> 2) & 127;
        const int c = idx & 3;
        const int row = ((buf == 0) ? m0 : n0) + r;
        uint32_t dst = sbase + buf * GS_BUF + r * 64 +
                       ((c ^ ((r >> 1) & 3)) << 4);
        cp_async16(dst, bufs[buf] + (size_t)row * K + k0 + c * 8);
    }
}

__global__ __launch_bounds__(256) void gemm_mma_kernel(
    const __half* __restrict__ Ah,
    const __half* __restrict__ Bh, const __half* __restrict__ Bl,
    const float* __restrict__ bias, float* __restrict__ Cf,
    __half* __restrict__ Ch,
    int M, int N, int K, int mode, int ntiles)
{
    extern __shared__ char smem[];
    const uint32_t sb = smem_u32(smem);
    const int tid = threadIdx.x;
    const int lane = tid & 31;
    const int wid = tid >> 5;
    const int warp_m = wid & 1;
    const int warp_n = wid >> 1;
    const int nbx = N >> 7;

    const int sub = lane >> 3;
    const int lane8 = lane & 7;
    const int a_roff = ((sub & 1) << 3) + lane8;
    const int a_csub = sub >> 1;
    const int b_noff = (((sub >> 1) & 1) << 3) + lane8;
    const int b_csub = sub & 1;
    const int groupID = lane >> 2;
    const int tig = lane & 3;

    // Hoisted fragment smem offsets (invariant across chunks AND tiles)
    uint32_t offA[2][4], offB[2][2];
#pragma unroll
    for (int ks = 0; ks < 2; ks++) {
#pragma unroll
        for (int im = 0; im < 4; im++) {
            int r = warp_m * 64 + im * 16 + a_roff;
            int cc = ks * 2 + a_csub;
            offA[ks][im] = r * 64 + ((cc ^ ((r >> 1) & 3)) << 4);
        }
#pragma unroll
        for (int in2 = 0; in2 < 2; in2++) {
            int n = warp_n * 32 + in2 * 16 + b_noff;
            int cc = ks * 2 + b_csub;
            offB[ks][in2] = n * 64 + ((cc ^ ((n >> 1) & 3)) << 4);
        }
    }

    const int NC = K / 32;   // 64

    for (int t = blockIdx.x; t < ntiles; t += gridDim.x) {
        const int m0 = (t / nbx) * 128;
        const int n0 = (t - (t / nbx) * nbx) * 128;

        float acc[4][4][4];
#pragma unroll
        for (int i = 0; i < 4; i++)
#pragma unroll
            for (int j = 0; j < 4; j++)
#pragma unroll
                for (int k = 0; k < 4; k++) acc[i][j][k] = 0.f;

        gemm_load_stage(sb,                Ah, Bh, Bl, m0, n0, K, 0,  tid); CP_COMMIT();
        gemm_load_stage(sb + GS_STAGE,     Ah, Bh, Bl, m0, n0, K, 32, tid); CP_COMMIT();
        gemm_load_stage(sb + 2 * GS_STAGE, Ah, Bh, Bl, m0, n0, K, 64, tid); CP_COMMIT();

        int slot = 0;
        for (int c = 0; c < NC; c++) {
            if (c + 3 <= NC)      { CP_WAIT(2); }
            else if (c + 2 == NC) { CP_WAIT(1); }
            else                  { CP_WAIT(0); }
            __syncthreads();
            if (c + 3 < NC) {
                gemm_load_stage(sb + ((c + 3) & 3) * GS_STAGE, Ah, Bh, Bl,
                                m0, n0, K, (c + 3) * 32, tid);
                CP_COMMIT();
            }
            const uint32_t st = sb + slot * GS_STAGE;
            slot = (slot + 1) & 3;

#pragma unroll
            for (int ks = 0; ks < 2; ks++) {
                uint32_t ah[4][4];
#pragma unroll
                for (int im = 0; im < 4; im++)
                    ldsm_x4(ah[im], st + offA[ks][im]);
                uint32_t bh[4][2], bl[4][2];
#pragma unroll
                for (int in2 = 0; in2 < 2; in2++) {
                    uint32_t tt[4];
                    ldsm_x4(tt, st + GS_BUF + offB[ks][in2]);
                    bh[in2 * 2][0] = tt[0]; bh[in2 * 2][1] = tt[1];
                    bh[in2 * 2 + 1][0] = tt[2]; bh[in2 * 2 + 1][1] = tt[3];
                    ldsm_x4(tt, st + 2 * GS_BUF + offB[ks][in2]);
                    bl[in2 * 2][0] = tt[0]; bl[in2 * 2][1] = tt[1];
                    bl[in2 * 2 + 1][0] = tt[2]; bl[in2 * 2 + 1][1] = tt[3];
                }
#pragma unroll
                for (int im = 0; im < 4; im++)
#pragma unroll
                    for (int in = 0; in < 4; in++) {
                        mma_f16(acc[im][in], ah[im], bh[in]);
                        mma_f16(acc[im][in], ah[im], bl[in]);
                    }
            }
        }

        // Epilogue: unscale 2^-20, add bias
#pragma unroll
        for (int im = 0; im < 4; im++) {
            int row0 = m0 + warp_m * 64 + im * 16 + groupID;
#pragma unroll
            for (int in = 0; in < 4; in++) {
                int col = n0 + warp_n * 32 + in * 8 + tig * 2;
                float2 bv = *(const float2*)&bias[col];
                float v00 = acc[im][in][0] * INV_S2 + bv.x;
                float v01 = acc[im][in][1] * INV_S2 + bv.y;
                float v10 = acc[im][in][2] * INV_S2 + bv.x;
                float v11 = acc[im][in][3] * INV_S2 + bv.y;
                if (mode == 0) {
                    *(float2*)&Cf[(size_t)row0 * N + col] = make_float2(v00, v01);
                    *(float2*)&Cf[(size_t)(row0 + 8) * N + col] = make_float2(v10, v11);
                } else {
                    *(uint32_t*)&Ch[(size_t)row0 * N + col] =
                        pack_h2(v00 * SCALE, v01 * SCALE);
                    *(uint32_t*)&Ch[(size_t)(row0 + 8) * N + col] =
                        pack_h2(v10 * SCALE, v11 * SCALE);
                }
            }
        }
    }
}

// ---------------------------------------------------------------------------
// Flash attention (causal) via fp16 mma.sync. (unchanged from R12)
// BM=128 q rows (8 warps, 256 threads), BN=64 keys. S = Qh*Kh; O += Ph*Vh.
// Smem: Q 32K + 2 x (Kh 16K | Vh 16K) = 96 KB. Double-buffered K/V.
// ---------------------------------------------------------------------------
#define AT_STAGE 32768
#define AT_SMEM (32768 + 2 * AT_STAGE)   // 98304

__global__ __launch_bounds__(256) void flash_attn_mma_kernel(
    const __half* __restrict__ qkv_hi,
    __half* __restrict__ ctx_hi)
{
    extern __shared__ char smem[];
    const uint32_t sb = smem_u32(smem);
    const uint32_t Qs = sb;

    const int qt = blockIdx.x;            // 0..7
    const int bh = blockIdx.y;            // 0..63
    const int b = bh >> 4, h = bh & 15;
    const int q0 = qt * 128;
    const int tid = threadIdx.x;
    const int lane = tid & 31;
    const int w = tid >> 5;               // 0..7

    const int sub = lane >> 3, lane8 = lane & 7;
    const int a_roff = ((sub & 1) << 3) + lane8;
    const int a_csub = sub >> 1;
    const int b_noff = (((sub >> 1) & 1) << 3) + lane8;
    const int b_csub = sub & 1;
    const int g = lane >> 2, tig = lane & 3;

    const size_t tok0 = (size_t)b * SEQ + q0;
    const size_t kbase = (size_t)b * SEQ;
    const int ktiles = 2 * qt + 2;

#pragma unroll
    for (int i = 0; i < 8; i++) {
        int idx = tid + i * 256;              // 0..2047
        int r = idx >> 4, c = idx & 15;
        uint32_t dst = Qs + r * 256 + ((c ^ (r & 7)) << 4);
        cp_async16(dst, qkv_hi + (tok0 + r) * E3 + h * HDIM + c * 8);
    }
    {
        const uint32_t S0 = sb + 32768;
#pragma unroll
        for (int i = 0; i < 8; i++) {
            int idx = tid + i * 256;
            int buf = idx >> 10;              // 0=K, 1=V
            int r = (idx >> 4) & 63, c = idx & 15;
            uint32_t sw = r * 256 + ((c ^ (r & 7)) << 4);
            size_t base = (kbase + r) * E3 + h * HDIM + c * 8 +
                          (size_t)(buf + 1) * EMB;
            cp_async16(S0 + buf * 16384 + sw, qkv_hi + base);
        }
    }
    CP_COMMIT();

    uint32_t qa[8][4];
    float oacc[16][4];
#pragma unroll
    for (int t = 0; t < 16; t++)
#pragma unroll
        for (int k = 0; k < 4; k++) oacc[t][k] = 0.f;
    float m0 = -INFINITY, m1 = -INFINITY, l0 = 0.f, l1 = 0.f;

    const float sc2 = 0.08838834764831845f * INV_S2;
    const int row0 = q0 + w * 16 + g;
    const int row1 = row0 + 8;

    for (int kt = 0; kt < ktiles; kt++) {
        CP_WAIT(0);
        __syncthreads();

        if (kt + 1 < ktiles) {
            const uint32_t S1 = sb + 32768 + ((kt + 1) & 1) * AT_STAGE;
            size_t kb0 = kbase + (size_t)(kt + 1) * 64;
#pragma unroll
            for (int i = 0; i < 8; i++) {
                int idx = tid + i * 256;
                int buf = idx >> 10;
                int r = (idx >> 4) & 63, c = idx & 15;
                uint32_t sw = r * 256 + ((c ^ (r & 7)) << 4);
                size_t base = (kb0 + r) * E3 + h * HDIM + c * 8 +
                              (size_t)(buf + 1) * EMB;
                cp_async16(S1 + buf * 16384 + sw, qkv_hi + base);
            }
            CP_COMMIT();
        }
        if (kt == 0) {
#pragma unroll
            for (int kc = 0; kc < 8; kc++) {
                int r = w * 16 + a_roff;
                int c = kc * 2 + a_csub;
                ldsm_x4(qa[kc], Qs + r * 256 + ((c ^ (r & 7)) << 4));
            }
        }

        const uint32_t Ks = sb + 32768 + (kt & 1) * AT_STAGE;
        const uint32_t Vh = Ks + 16384;

        float sacc[8][4];
#pragma unroll
        for (int j = 0; j < 8; j++)
#pragma unroll
            for (int k = 0; k < 4; k++) sacc[j][k] = 0.f;
#pragma unroll
        for (int kc = 0; kc < 8; kc++) {
#pragma unroll
            for (int jn = 0; jn < 4; jn++) {
                int r = jn * 16 + b_noff;
                int c = kc * 2 + b_csub;
                uint32_t kb[4];
                ldsm_x4(kb, Ks + r * 256 + ((c ^ (r & 7)) << 4));
                mma_f16(sacc[jn * 2],     qa[kc], kb);
                mma_f16(sacc[jn * 2 + 1], qa[kc], kb + 2);
            }
        }

        const bool domask = (kt * 64 + 63) > (q0 + w * 16);
        float mx0 = -INFINITY, mx1 = -INFINITY;
#pragma unroll
        for (int j = 0; j < 8; j++) {
            int col = kt * 64 + j * 8 + tig * 2;
            float s0 = sacc[j][0] * sc2, s1 = sacc[j][1] * sc2;
            float s2 = sacc[j][2] * sc2, s3 = sacc[j][3] * sc2;
            if (domask) {
                if (col > row0)     s0 = -1e30f;
                if (col + 1 > row0) s1 = -1e30f;
                if (col > row1)     s2 = -1e30f;
                if (col + 1 > row1) s3 = -1e30f;
            }
            sacc[j][0] = s0; sacc[j][1] = s1; sacc[j][2] = s2; sacc[j][3] = s3;
            mx0 = fmaxf(mx0, fmaxf(s0, s1));
            mx1 = fmaxf(mx1, fmaxf(s2, s3));
        }
        mx0 = fmaxf(mx0, __shfl_xor_sync(0xffffffffu, mx0, 1));
        mx0 = fmaxf(mx0, __shfl_xor_sync(0xffffffffu, mx0, 2));
        mx1 = fmaxf(mx1, __shfl_xor_sync(0xffffffffu, mx1, 1));
        mx1 = fmaxf(mx1, __shfl_xor_sync(0xffffffffu, mx1, 2));

        float mn0 = fmaxf(m0, mx0), mn1 = fmaxf(m1, mx1);
        float al0 = __expf(m0 - mn0), al1 = __expf(m1 - mn1);
        m0 = mn0; m1 = mn1;

        float sum0 = 0.f, sum1 = 0.f;
#pragma unroll
        for (int j = 0; j < 8; j++) {
            float p0 = __expf(sacc[j][0] - mn0);
            float p1 = __expf(sacc[j][1] - mn0);
            float p2 = __expf(sacc[j][2] - mn1);
            float p3 = __expf(sacc[j][3] - mn1);
            sacc[j][0] = p0; sacc[j][1] = p1; sacc[j][2] = p2; sacc[j][3] = p3;
            sum0 += p0 + p1; sum1 += p2 + p3;
        }
        sum0 += __shfl_xor_sync(0xffffffffu, sum0, 1);
        sum0 += __shfl_xor_sync(0xffffffffu, sum0, 2);
        sum1 += __shfl_xor_sync(0xffffffffu, sum1, 1);
        sum1 += __shfl_xor_sync(0xffffffffu, sum1, 2);
        l0 = l0 * al0 + sum0;
        l1 = l1 * al1 + sum1;

#pragma unroll
        for (int t = 0; t < 16; t++) {
            oacc[t][0] *= al0; oacc[t][1] *= al0;
            oacc[t][2] *= al1; oacc[t][3] *= al1;
        }

        uint32_t phi[4][4];
#pragma unroll
        for (int kc = 0; kc < 4; kc++) {
            int t0 = kc * 2, t1 = kc * 2 + 1;
            phi[kc][0] = pack_h2(sacc[t0][0], sacc[t0][1]);
            phi[kc][1] = pack_h2(sacc[t0][2], sacc[t0][3]);
            phi[kc][2] = pack_h2(sacc[t1][0], sacc[t1][1]);
            phi[kc][3] = pack_h2(sacc[t1][2], sacc[t1][3]);
        }

#pragma unroll
        for (int kc = 0; kc < 4; kc++) {
#pragma unroll
            for (int jd = 0; jd < 8; jd++) {
                int r = kc * 16 + a_roff;
                int c = jd * 2 + a_csub;
                uint32_t off = r * 256 + ((c ^ (r & 7)) << 4);
                uint32_t vh2[4];
                ldsm_x4_t(vh2, Vh + off);
                mma_f16(oacc[jd * 2], phi[kc], vh2);
                mma_f16(oacc[jd * 2 + 1], phi[kc], vh2 + 2);
            }
        }
    }

    float inv0 = 1.f / l0, inv1 = 1.f / l1;
    size_t tr0 = tok0 + w * 16 + g;
    size_t tr1 = tr0 + 8;
#pragma unroll
    for (int jd = 0; jd < 16; jd++) {
        int col = h * HDIM + jd * 8 + tig * 2;
        *(uint32_t*)&ctx_hi[tr0 * EMB + col] =
            pack_h2(oacc[jd][0] * inv0, oacc[jd][1] * inv0);
        *(uint32_t*)&ctx_hi[tr1 * EMB + col] =
            pack_h2(oacc[jd][2] * inv1, oacc[jd][3] * inv1);
    }
}

// ---------------------------------------------------------------------------
// Launch
// ---------------------------------------------------------------------------
extern "C" void kernel_launch(void* const* d_in, const int* in_sizes, int n_in,
                              void* d_out, int out_size)
{
    const float* hidden = (const float*)d_in[0];
    const float* wqkv   = (const float*)d_in[1];
    const float* bqkv   = (const float*)d_in[2];
    const float* wproj  = (const float*)d_in[3];
    const float* bproj  = (const float*)d_in[4];
    float* out = (float*)d_out;

    __half *hid_hi, *wqkvt_hi, *wqkvt_lo, *wprojt_hi, *wprojt_lo;
    __half *qkv_hi, *ctx_hi;
    cudaGetSymbolAddress((void**)&hid_hi, g_hid_hi);
    cudaGetSymbolAddress((void**)&wqkvt_hi, g_wqkvt_hi);
    cudaGetSymbolAddress((void**)&wqkvt_lo, g_wqkvt_lo);
    cudaGetSymbolAddress((void**)&wprojt_hi, g_wprojt_hi);
    cudaGetSymbolAddress((void**)&wprojt_lo, g_wprojt_lo);
    cudaGetSymbolAddress((void**)&qkv_hi, g_qkv_hi);
    cudaGetSymbolAddress((void**)&ctx_hi, g_ctx_hi);

    cudaFuncSetAttribute(gemm_mma_kernel,
                         cudaFuncAttributeMaxDynamicSharedMemorySize,
                         GSMEM_TOTAL);
    cudaFuncSetAttribute(flash_attn_mma_kernel,
                         cudaFuncAttributeMaxDynamicSharedMemorySize,
                         AT_SMEM);

    // 0) Convert hidden (hi only); transpose+split weights
    {
        int n4 = TOTAL * EMB / 4;
        convert_hi_kernel<<<(n4 + 255) / 256, 256>>>(hidden, hid_hi, n4);
        dim3 blk(32, 8);
        transpose_split_kernel<<<dim3(E3 / 32, EMB / 32), blk>>>(
            wqkv, wqkvt_hi, wqkvt_lo, EMB, E3);
        transpose_split_kernel<<<dim3(EMB / 32, EMB / 32), blk>>>(
            wproj, wprojt_hi, wprojt_lo, EMB, EMB);
    }
    // 1) QKV GEMM (persistent, 1536 tiles over 296 CTAs) -> fp16 qkv_hi
    {
        int ntiles = (E3 / 128) * (TOTAL / 128);   // 1536
        gemm_mma_kernel<<<NSM_SLOTS, 256, GSMEM_TOTAL>>>(
            hid_hi, wqkvt_hi, wqkvt_lo, bqkv,
            nullptr, qkv_hi, TOTAL, E3, EMB, 1, ntiles);
    }
    // 2) Flash attention (BM=128, 8 warps) -> ctx_hi (scaled by 1024)
    {
        dim3 grid(SEQ / 128, BATCH * HEADS);
        flash_attn_mma_kernel<<<grid, 256, AT_SMEM>>>(qkv_hi, ctx_hi);
    }
    // 3) Proj GEMM (persistent, 512 tiles over 296 CTAs) -> fp32 out
    {
        int ntiles = (EMB / 128) * (TOTAL / 128);  // 512
        gemm_mma_kernel<<<NSM_SLOTS, 256, GSMEM_TOTAL>>>(
            ctx_hi, wprojt_hi, wprojt_lo, bproj,
            out, nullptr, TOTAL, EMB, EMB, 0, ntiles);
    }
}

// round 16
// speedup vs baseline: 1.6567x; 1.6567x over previous
#include <cuda_runtime.h>
#include <cuda_bf16.h>
#include <cuda_fp16.h>
#include <math.h>
#include <stdint.h>

// Problem constants (fixed by dataset)
#define BATCH 4
#define SEQ   1024
#define HEADS 16
#define HDIM  128
#define EMB   (HEADS * HDIM)        // 2048
#define TOTAL (BATCH * SEQ)         // 4096
#define E3    (3 * EMB)             // 6144

#define SCALE     1024.0f
#define INV_S2    (1.0f / 1048576.0f)

// ---------------------------------------------------------------------------
// Device scratch (allocation-free rule: __device__ globals)
// ---------------------------------------------------------------------------
__device__ __half g_hid_hi[(size_t)TOTAL * EMB];          // 1024*hidden
__device__ __half g_wqkvt_hi[(size_t)E3 * EMB];           // [N=6144,K=2048]
__device__ __half g_wprojt_hi[(size_t)EMB * EMB];         // [N=2048,K=2048]
__device__ __half g_qkv_hi[(size_t)TOTAL * E3];           // 1024*qkv
__device__ __half g_ctx_hi[(size_t)TOTAL * EMB];          // 1024*ctx

// ---------------------------------------------------------------------------
// PTX helpers
// ---------------------------------------------------------------------------
__device__ __forceinline__ uint32_t smem_u32(const void* p) {
    uint32_t a;
    asm("{ .reg .u64 t; cvta.to.shared.u64 t, %1; cvt.u32.u64 %0, t; }"
        : "=r"(a) : "l"(p));
    return a;
}
__device__ __forceinline__ void cp_async16(uint32_t dst, const void* src) {
    asm volatile("cp.async.cg.shared.global [%0], [%1], 16;"
                 :: "r"(dst), "l"(src) : "memory");
}
#define CP_COMMIT() asm volatile("cp.async.commit_group;" ::: "memory")
#define CP_WAIT(n)  asm volatile("cp.async.wait_group %0;" :: "n"(n) : "memory")

__device__ __forceinline__ void ldsm_x4(uint32_t* r, uint32_t addr) {
    asm volatile("ldmatrix.sync.aligned.m8n8.x4.shared.b16 {%0,%1,%2,%3}, [%4];"
                 : "=r"(r[0]), "=r"(r[1]), "=r"(r[2]), "=r"(r[3]) : "r"(addr));
}
__device__ __forceinline__ void ldsm_x4_t(uint32_t* r, uint32_t addr) {
    asm volatile("ldmatrix.sync.aligned.m8n8.x4.trans.shared.b16 {%0,%1,%2,%3}, [%4];"
                 : "=r"(r[0]), "=r"(r[1]), "=r"(r[2]), "=r"(r[3]) : "r"(addr));
}
__device__ __forceinline__ void mma_f16(float* d, const uint32_t* a,
                                        const uint32_t* b) {
    asm volatile(
        "mma.sync.aligned.m16n8k16.row.col.f32.f16.f16.f32 "
        "{%0,%1,%2,%3}, {%4,%5,%6,%7}, {%8,%9}, {%0,%1,%2,%3};"
        : "+f"(d[0]), "+f"(d[1]), "+f"(d[2]), "+f"(d[3])
        : "r"(a[0]), "r"(a[1]), "r"(a[2]), "r"(a[3]), "r"(b[0]), "r"(b[1]));
}
__device__ __forceinline__ uint32_t pack_h2(float x, float y) {
    __half2 t = __floats2half2_rn(x, y);
    return *(uint32_t*)&t;
}

// ---------------------------------------------------------------------------
// Convert (hi only): H = fp16(1024 * X)
// ---------------------------------------------------------------------------
__global__ void convert_hi_kernel(const float* __restrict__ X,
                                  __half* __restrict__ H, int n4)
{
    int i = blockIdx.x * blockDim.x + threadIdx.x;
    if (i >= n4) return;
    float4 v = ((const float4*)X)[i];
    uint32_t o[2];
    o[0] = pack_h2(v.x * SCALE, v.y * SCALE);
    o[1] = pack_h2(v.z * SCALE, v.w * SCALE);
    *(uint2*)(H + i * 4) = *(uint2*)o;
}

// ---------------------------------------------------------------------------
// Transpose: X[K,N] fp32 -> T[N,K] fp16 of (1024*X)   (hi only)
// ---------------------------------------------------------------------------
__global__ void transpose_hi_kernel(const float* __restrict__ X,
                                    __half* __restrict__ TH,
                                    int K, int N)
{
    __shared__ float tile[32][33];
    int n0 = blockIdx.x * 32, k0 = blockIdx.y * 32;
    int tx = threadIdx.x, ty = threadIdx.y;
#pragma unroll
    for (int i = 0; i < 4; i++)
        tile[ty + i * 8][tx] = X[(size_t)(k0 + ty + i * 8) * N + n0 + tx];
    __syncthreads();
#pragma unroll
    for (int i = 0; i < 4; i++) {
        int n = n0 + ty + i * 8;
        int k = k0 + tx;
        TH[(size_t)n * K + k] = __float2half_rn(tile[tx][ty + i * 8] * SCALE);
    }
}

// ---------------------------------------------------------------------------
// fp16 single-product GEMM via mma.sync: C = Ah @ Bh^T * 2^-20 + bias
// BM=BN=128, BK=32, 256 threads, 8 warps (2x4), warp tile 64x32.
// 4-stage cp.async ring. Stage: Ah | Bh = 16KB. Total smem 64KB.
// mode 0: fp32 Cf out. mode 1: fp16 Ch out (scaled by 1024).
// ---------------------------------------------------------------------------
#define GS_BUF   8192
#define GS_STAGE 16384
#define GS_NSTG  4
#define GSMEM_TOTAL (GS_NSTG * GS_STAGE)   // 64 KB

__device__ __forceinline__ void gemm_load_stage(
    uint32_t sbase, const __half* __restrict__ Ah,
    const __half* __restrict__ Bh,
    int m0, int n0, int K, int k0, int tid)
{
    const __half* bufs[2] = {Ah, Bh};
#pragma unroll
    for (int i = 0; i < 4; i++) {
        const int idx = tid + i * 256;        // 0..1023
        const int buf = idx >> 9;             // 0..1
        const int r = (idx >> 2) & 127;
        const int c = idx & 3;
        const int row = ((buf == 0) ? m0 : n0) + r;
        uint32_t dst = sbase + buf * GS_BUF + r * 64 +
                       ((c ^ ((r >> 1) & 3)) << 4);
        cp_async16(dst, bufs[buf] + (size_t)row * K + k0 + c * 8);
    }
}

__global__ __launch_bounds__(256) void gemm_mma_kernel(
    const __half* __restrict__ Ah, const __half* __restrict__ Bh,
    const float* __restrict__ bias, float* __restrict__ Cf,
    __half* __restrict__ Ch,
    int M, int N, int K, int mode)
{
    extern __shared__ char smem[];
    const uint32_t sb = smem_u32(smem);
    const int tid = threadIdx.x;
    const int lane = tid & 31;
    const int wid = tid >> 5;
    const int warp_m = wid & 1;
    const int warp_n = wid >> 1;
    const int m0 = blockIdx.y * 128;
    const int n0 = blockIdx.x * 128;

    const int sub = lane >> 3;
    const int lane8 = lane & 7;
    const int a_roff = ((sub & 1) << 3) + lane8;
    const int a_csub = sub >> 1;
    const int b_noff = (((sub >> 1) & 1) << 3) + lane8;
    const int b_csub = sub & 1;
    const int groupID = lane >> 2;
    const int tig = lane & 3;

    // Hoisted fragment smem offsets (invariant across chunks)
    uint32_t offA[2][4], offB[2][2];
#pragma unroll
    for (int ks = 0; ks < 2; ks++) {
#pragma unroll
        for (int im = 0; im < 4; im++) {
            int r = warp_m * 64 + im * 16 + a_roff;
            int cc = ks * 2 + a_csub;
            offA[ks][im] = r * 64 + ((cc ^ ((r >> 1) & 3)) << 4);
        }
#pragma unroll
        for (int in2 = 0; in2 < 2; in2++) {
            int n = warp_n * 32 + in2 * 16 + b_noff;
            int cc = ks * 2 + b_csub;
            offB[ks][in2] = n * 64 + ((cc ^ ((n >> 1) & 3)) << 4);
        }
    }

    float acc[4][4][4];
#pragma unroll
    for (int i = 0; i < 4; i++)
#pragma unroll
        for (int j = 0; j < 4; j++)
#pragma unroll
            for (int k = 0; k < 4; k++) acc[i][j][k] = 0.f;

    const int NC = K / 32;   // 64
    gemm_load_stage(sb,                Ah, Bh, m0, n0, K, 0,  tid); CP_COMMIT();
    gemm_load_stage(sb + GS_STAGE,     Ah, Bh, m0, n0, K, 32, tid); CP_COMMIT();
    gemm_load_stage(sb + 2 * GS_STAGE, Ah, Bh, m0, n0, K, 64, tid); CP_COMMIT();

    int slot = 0;
    for (int c = 0; c < NC; c++) {
        if (c + 3 <= NC)      { CP_WAIT(2); }
        else if (c + 2 == NC) { CP_WAIT(1); }
        else                  { CP_WAIT(0); }
        __syncthreads();
        if (c + 3 < NC) {
            gemm_load_stage(sb + ((c + 3) & 3) * GS_STAGE, Ah, Bh,
                            m0, n0, K, (c + 3) * 32, tid);
            CP_COMMIT();
        }
        const uint32_t st = sb + slot * GS_STAGE;
        slot = (slot + 1) & 3;

#pragma unroll
        for (int ks = 0; ks < 2; ks++) {
            uint32_t ah[4][4];
#pragma unroll
            for (int im = 0; im < 4; im++)
                ldsm_x4(ah[im], st + offA[ks][im]);
            uint32_t bh[4][2];
#pragma unroll
            for (int in2 = 0; in2 < 2; in2++) {
                uint32_t tt[4];
                ldsm_x4(tt, st + GS_BUF + offB[ks][in2]);
                bh[in2 * 2][0] = tt[0]; bh[in2 * 2][1] = tt[1];
                bh[in2 * 2 + 1][0] = tt[2]; bh[in2 * 2 + 1][1] = tt[3];
            }
#pragma unroll
            for (int im = 0; im < 4; im++)
#pragma unroll
                for (int in = 0; in < 4; in++)
                    mma_f16(acc[im][in], ah[im], bh[in]);
        }
    }

    // Epilogue: unscale 2^-20, add bias
#pragma unroll
    for (int im = 0; im < 4; im++) {
        int row0 = m0 + warp_m * 64 + im * 16 + groupID;
#pragma unroll
        for (int in = 0; in < 4; in++) {
            int col = n0 + warp_n * 32 + in * 8 + tig * 2;
            float2 bv = *(const float2*)&bias[col];
            float v00 = acc[im][in][0] * INV_S2 + bv.x;
            float v01 = acc[im][in][1] * INV_S2 + bv.y;
            float v10 = acc[im][in][2] * INV_S2 + bv.x;
            float v11 = acc[im][in][3] * INV_S2 + bv.y;
            if (mode == 0) {
                *(float2*)&Cf[(size_t)row0 * N + col] = make_float2(v00, v01);
                *(float2*)&Cf[(size_t)(row0 + 8) * N + col] = make_float2(v10, v11);
            } else {
                *(uint32_t*)&Ch[(size_t)row0 * N + col] =
                    pack_h2(v00 * SCALE, v01 * SCALE);
                *(uint32_t*)&Ch[(size_t)(row0 + 8) * N + col] =
                    pack_h2(v10 * SCALE, v11 * SCALE);
            }
        }
    }
}

// ---------------------------------------------------------------------------
// Flash attention (causal) via fp16 mma.sync. (R12 structure, unchanged)
// BM=128 q rows (8 warps, 256 threads), BN=64 keys. S = Qh*Kh; O += Ph*Vh.
// Smem: Q 32K + 2 x (Kh 16K | Vh 16K) = 96 KB. Double-buffered K/V.
// ---------------------------------------------------------------------------
#define AT_STAGE 32768
#define AT_SMEM (32768 + 2 * AT_STAGE)   // 98304

__global__ __launch_bounds__(256) void flash_attn_mma_kernel(
    const __half* __restrict__ qkv_hi,
    __half* __restrict__ ctx_hi)
{
    extern __shared__ char smem[];
    const uint32_t sb = smem_u32(smem);
    const uint32_t Qs = sb;

    const int qt = blockIdx.x;            // 0..7
    const int bh = blockIdx.y;            // 0..63
    const int b = bh >> 4, h = bh & 15;
    const int q0 = qt * 128;
    const int tid = threadIdx.x;
    const int lane = tid & 31;
    const int w = tid >> 5;               // 0..7

    const int sub = lane >> 3, lane8 = lane & 7;
    const int a_roff = ((sub & 1) << 3) + lane8;
    const int a_csub = sub >> 1;
    const int b_noff = (((sub >> 1) & 1) << 3) + lane8;
    const int b_csub = sub & 1;
    const int g = lane >> 2, tig = lane & 3;

    const size_t tok0 = (size_t)b * SEQ + q0;
    const size_t kbase = (size_t)b * SEQ;
    const int ktiles = 2 * qt + 2;

#pragma unroll
    for (int i = 0; i < 8; i++) {
        int idx = tid + i * 256;              // 0..2047
        int r = idx >> 4, c = idx & 15;
        uint32_t dst = Qs + r * 256 + ((c ^ (r & 7)) << 4);
        cp_async16(dst, qkv_hi + (tok0 + r) * E3 + h * HDIM + c * 8);
    }
    {
        const uint32_t S0 = sb + 32768;
#pragma unroll
        for (int i = 0; i < 8; i++) {
            int idx = tid + i * 256;
            int buf = idx >> 10;              // 0=K, 1=V
            int r = (idx >> 4) & 63, c = idx & 15;
            uint32_t sw = r * 256 + ((c ^ (r & 7)) << 4);
            size_t base = (kbase + r) * E3 + h * HDIM + c * 8 +
                          (size_t)(buf + 1) * EMB;
            cp_async16(S0 + buf * 16384 + sw, qkv_hi + base);
        }
    }
    CP_COMMIT();

    uint32_t qa[8][4];
    float oacc[16][4];
#pragma unroll
    for (int t = 0; t < 16; t++)
#pragma unroll
        for (int k = 0; k < 4; k++) oacc[t][k] = 0.f;
    float m0 = -INFINITY, m1 = -INFINITY, l0 = 0.f, l1 = 0.f;

    const float sc2 = 0.08838834764831845f * INV_S2;
    const int row0 = q0 + w * 16 + g;
    const int row1 = row0 + 8;

    for (int kt = 0; kt < ktiles; kt++) {
        CP_WAIT(0);
        __syncthreads();

        if (kt + 1 < ktiles) {
            const uint32_t S1 = sb + 32768 + ((kt + 1) & 1) * AT_STAGE;
            size_t kb0 = kbase + (size_t)(kt + 1) * 64;
#pragma unroll
            for (int i = 0; i < 8; i++) {
                int idx = tid + i * 256;
                int buf = idx >> 10;
                int r = (idx >> 4) & 63, c = idx & 15;
                uint32_t sw = r * 256 + ((c ^ (r & 7)) << 4);
                size_t base = (kb0 + r) * E3 + h * HDIM + c * 8 +
                              (size_t)(buf + 1) * EMB;
                cp_async16(S1 + buf * 16384 + sw, qkv_hi + base);
            }
            CP_COMMIT();
        }
        if (kt == 0) {
#pragma unroll
            for (int kc = 0; kc < 8; kc++) {
                int r = w * 16 + a_roff;
                int c = kc * 2 + a_csub;
                ldsm_x4(qa[kc], Qs + r * 256 + ((c ^ (r & 7)) << 4));
            }
        }

        const uint32_t Ks = sb + 32768 + (kt & 1) * AT_STAGE;
        const uint32_t Vh = Ks + 16384;

        float sacc[8][4];
#pragma unroll
        for (int j = 0; j < 8; j++)
#pragma unroll
            for (int k = 0; k < 4; k++) sacc[j][k] = 0.f;
#pragma unroll
        for (int kc = 0; kc < 8; kc++) {
#pragma unroll
            for (int jn = 0; jn < 4; jn++) {
                int r = jn * 16 + b_noff;
                int c = kc * 2 + b_csub;
                uint32_t kb[4];
                ldsm_x4(kb, Ks + r * 256 + ((c ^ (r & 7)) << 4));
                mma_f16(sacc[jn * 2],     qa[kc], kb);
                mma_f16(sacc[jn * 2 + 1], qa[kc], kb + 2);
            }
        }

        const bool domask = (kt * 64 + 63) > (q0 + w * 16);
        float mx0 = -INFINITY, mx1 = -INFINITY;
#pragma unroll
        for (int j = 0; j < 8; j++) {
            int col = kt * 64 + j * 8 + tig * 2;
            float s0 = sacc[j][0] * sc2, s1 = sacc[j][1] * sc2;
            float s2 = sacc[j][2] * sc2, s3 = sacc[j][3] * sc2;
            if (domask) {
                if (col > row0)     s0 = -1e30f;
                if (col + 1 > row0) s1 = -1e30f;
                if (col > row1)     s2 = -1e30f;
                if (col + 1 > row1) s3 = -1e30f;
            }
            sacc[j][0] = s0; sacc[j][1] = s1; sacc[j][2] = s2; sacc[j][3] = s3;
            mx0 = fmaxf(mx0, fmaxf(s0, s1));
            mx1 = fmaxf(mx1, fmaxf(s2, s3));
        }
        mx0 = fmaxf(mx0, __shfl_xor_sync(0xffffffffu, mx0, 1));
        mx0 = fmaxf(mx0, __shfl_xor_sync(0xffffffffu, mx0, 2));
        mx1 = fmaxf(mx1, __shfl_xor_sync(0xffffffffu, mx1, 1));
        mx1 = fmaxf(mx1, __shfl_xor_sync(0xffffffffu, mx1, 2));

        float mn0 = fmaxf(m0, mx0), mn1 = fmaxf(m1, mx1);
        float al0 = __expf(m0 - mn0), al1 = __expf(m1 - mn1);
        m0 = mn0; m1 = mn1;

        float sum0 = 0.f, sum1 = 0.f;
#pragma unroll
        for (int j = 0; j < 8; j++) {
            float p0 = __expf(sacc[j][0] - mn0);
            float p1 = __expf(sacc[j][1] - mn0);
            float p2 = __expf(sacc[j][2] - mn1);
            float p3 = __expf(sacc[j][3] - mn1);
            sacc[j][0] = p0; sacc[j][1] = p1; sacc[j][2] = p2; sacc[j][3] = p3;
            sum0 += p0 + p1; sum1 += p2 + p3;
        }
        sum0 += __shfl_xor_sync(0xffffffffu, sum0, 1);
        sum0 += __shfl_xor_sync(0xffffffffu, sum0, 2);
        sum1 += __shfl_xor_sync(0xffffffffu, sum1, 1);
        sum1 += __shfl_xor_sync(0xffffffffu, sum1, 2);
        l0 = l0 * al0 + sum0;
        l1 = l1 * al1 + sum1;

#pragma unroll
        for (int t = 0; t < 16; t++) {
            oacc[t][0] *= al0; oacc[t][1] *= al0;
            oacc[t][2] *= al1; oacc[t][3] *= al1;
        }

        uint32_t phi[4][4];
#pragma unroll
        for (int kc = 0; kc < 4; kc++) {
            int t0 = kc * 2, t1 = kc * 2 + 1;
            phi[kc][0] = pack_h2(sacc[t0][0], sacc[t0][1]);
            phi[kc][1] = pack_h2(sacc[t0][2], sacc[t0][3]);
            phi[kc][2] = pack_h2(sacc[t1][0], sacc[t1][1]);
            phi[kc][3] = pack_h2(sacc[t1][2], sacc[t1][3]);
        }

#pragma unroll
        for (int kc = 0; kc < 4; kc++) {
#pragma unroll
            for (int jd = 0; jd < 8; jd++) {
                int r = kc * 16 + a_roff;
                int c = jd * 2 + a_csub;
                uint32_t off = r * 256 + ((c ^ (r & 7)) << 4);
                uint32_t vh2[4];
                ldsm_x4_t(vh2, Vh + off);
                mma_f16(oacc[jd * 2], phi[kc], vh2);
                mma_f16(oacc[jd * 2 + 1], phi[kc], vh2 + 2);
            }
        }
    }

    float inv0 = 1.f / l0, inv1 = 1.f / l1;
    size_t tr0 = tok0 + w * 16 + g;
    size_t tr1 = tr0 + 8;
#pragma unroll
    for (int jd = 0; jd < 16; jd++) {
        int col = h * HDIM + jd * 8 + tig * 2;
        *(uint32_t*)&ctx_hi[tr0 * EMB + col] =
            pack_h2(oacc[jd][0] * inv0, oacc[jd][1] * inv0);
        *(uint32_t*)&ctx_hi[tr1 * EMB + col] =
            pack_h2(oacc[jd][2] * inv1, oacc[jd][3] * inv1);
    }
}

// ---------------------------------------------------------------------------
// Launch
// ---------------------------------------------------------------------------
extern "C" void kernel_launch(void* const* d_in, const int* in_sizes, int n_in,
                              void* d_out, int out_size)
{
    const float* hidden = (const float*)d_in[0];
    const float* wqkv   = (const float*)d_in[1];
    const float* bqkv   = (const float*)d_in[2];
    const float* wproj  = (const float*)d_in[3];
    const float* bproj  = (const float*)d_in[4];
    float* out = (float*)d_out;

    __half *hid_hi, *wqkvt_hi, *wprojt_hi, *qkv_hi, *ctx_hi;
    cudaGetSymbolAddress((void**)&hid_hi, g_hid_hi);
    cudaGetSymbolAddress((void**)&wqkvt_hi, g_wqkvt_hi);
    cudaGetSymbolAddress((void**)&wprojt_hi, g_wprojt_hi);
    cudaGetSymbolAddress((void**)&qkv_hi, g_qkv_hi);
    cudaGetSymbolAddress((void**)&ctx_hi, g_ctx_hi);

    cudaFuncSetAttribute(gemm_mma_kernel,
                         cudaFuncAttributeMaxDynamicSharedMemorySize,
                         GSMEM_TOTAL);
    cudaFuncSetAttribute(flash_attn_mma_kernel,
                         cudaFuncAttributeMaxDynamicSharedMemorySize,
                         AT_SMEM);

    // 0) Convert hidden (hi only); transpose weights (hi only)
    {
        int n4 = TOTAL * EMB / 4;
        convert_hi_kernel<<<(n4 + 255) / 256, 256>>>(hidden, hid_hi, n4);
        dim3 blk(32, 8);
        transpose_hi_kernel<<<dim3(E3 / 32, EMB / 32), blk>>>(
            wqkv, wqkvt_hi, EMB, E3);
        transpose_hi_kernel<<<dim3(EMB / 32, EMB / 32), blk>>>(
            wproj, wprojt_hi, EMB, EMB);
    }
    // 1) QKV GEMM (single product) -> fp16 qkv_hi (bias folded, scaled 1024)
    {
        dim3 grid(E3 / 128, TOTAL / 128);
        gemm_mma_kernel<<<grid, 256, GSMEM_TOTAL>>>(
            hid_hi, wqkvt_hi, bqkv, nullptr, qkv_hi, TOTAL, E3, EMB, 1);
    }
    // 2) Flash attention (BM=128, 8 warps) -> ctx_hi (scaled by 1024)
    {
        dim3 grid(SEQ / 128, BATCH * HEADS);
        flash_attn_mma_kernel<<<grid, 256, AT_SMEM>>>(qkv_hi, ctx_hi);
    }
    // 3) Proj GEMM (single product) -> fp32 out
    {
        dim3 grid(EMB / 128, TOTAL / 128);
        gemm_mma_kernel<<<grid, 256, GSMEM_TOTAL>>>(
            ctx_hi, wprojt_hi, bproj, out, nullptr, TOTAL, EMB, EMB, 0);
    }
}